// round 2
// baseline (speedup 1.0000x reference)
#include <cuda_runtime.h>
#include <cuda_bf16.h>
#include <stdint.h>

#define N_NODES_C  100000
#define N_GRAPHS_C 128
#define D_NODE 96
#define D_EDGE 32
#define HID 16
#define BN_EPS 1e-5f

#define ET 256        // edges per block (== threads)
#define ST 257        // padded shared stride for attr transpose (conflict-free)
#define NT 128        // node-kernel threads

// -------- scratch (no allocations allowed) --------
__device__ float g_p[N_NODES_C * HID];     // per-node folded first-layer partials (6.4 MB)
__device__ float g_Wx[HID * D_NODE];       // folded W1 (node part), [k][j]
__device__ float g_WeT[D_EDGE * HID];      // folded W1 (edge part), TRANSPOSED [j][k]
__device__ float g_bf[HID];                // folded bias (b1, BN)
__device__ float g_w2[HID];
__device__ float g_b2;

// -------- fold BN into weights --------
__global__ void prep_kernel(const float* __restrict__ W1, const float* __restrict__ b1,
                            const float* __restrict__ gamma, const float* __restrict__ beta,
                            const float* __restrict__ rm, const float* __restrict__ rv,
                            const float* __restrict__ W2, const float* __restrict__ b2) {
    __shared__ float a[HID];
    int t = threadIdx.x;
    if (t < HID) {
        float ak = gamma[t] * rsqrtf(rv[t] + BN_EPS);
        a[t] = ak;
        g_bf[t] = ak * (b1[t] - rm[t]) + beta[t];
        g_w2[t] = W2[t];
    }
    if (t == 0) g_b2 = b2[0];
    __syncthreads();
    for (int i = t; i < HID * D_NODE; i += blockDim.x) {
        int k = i / D_NODE, j = i % D_NODE;
        g_Wx[i] = a[k] * W1[k * (D_NODE + D_EDGE) + j];
    }
    for (int i = t; i < D_EDGE * HID; i += blockDim.x) {
        int j = i / HID, k = i % HID;               // g_WeT[j*16+k]
        g_WeT[i] = a[k] * W1[k * (D_NODE + D_EDGE) + D_NODE + j];
    }
}

__global__ void zero_kernel(float* __restrict__ out, int n) {
    int i = blockIdx.x * blockDim.x + threadIdx.x;
    if (i < n) out[i] = 0.0f;
}

// -------- per-node: p[n][k] = Wx'[k] . x[n] --------
__global__ void node_kernel(const float* __restrict__ x, int n_nodes) {
    __shared__ float sW[HID * D_NODE];      // 6 KB
    for (int i = threadIdx.x; i < HID * D_NODE; i += blockDim.x) sW[i] = g_Wx[i];
    __syncthreads();
    int n = blockIdx.x * blockDim.x + threadIdx.x;
    if (n >= n_nodes) return;
    float acc[HID];
#pragma unroll
    for (int k = 0; k < HID; k++) acc[k] = 0.0f;
    const float4* xr = (const float4*)(x + (size_t)n * D_NODE);
#pragma unroll
    for (int jj = 0; jj < D_NODE / 4; jj++) {
        float4 v = __ldg(xr + jj);
#pragma unroll
        for (int k = 0; k < HID; k++) {
            const float4 w = *(const float4*)(sW + k * D_NODE + jj * 4);
            acc[k] += w.x * v.x + w.y * v.y + w.z * v.z + w.w * v.w;
        }
    }
    float4* po = (float4*)(g_p + (size_t)n * HID);
    po[0] = make_float4(acc[0], acc[1], acc[2], acc[3]);
    po[1] = make_float4(acc[4], acc[5], acc[6], acc[7]);
    po[2] = make_float4(acc[8], acc[9], acc[10], acc[11]);
    po[3] = make_float4(acc[12], acc[13], acc[14], acc[15]);
}

// -------- per-edge: msg + pooled accumulation --------
__global__ void __launch_bounds__(ET) edge_kernel(
    const float* __restrict__ edge_attr,
    const int* __restrict__ ei,             // [2][E] int32 (JAX x64 disabled)
    const int* __restrict__ batch,          // [N]    int32
    float* __restrict__ out,                // [G]
    int n_edges) {
    __shared__ float sAttrT[D_EDGE * ST];   // transposed attr tile, ~32.9 KB
    __shared__ float sW[D_EDGE * HID];      // WeT [j][k], 2 KB
    __shared__ float sB[HID];
    __shared__ float sW2[HID];
    __shared__ float bins[N_GRAPHS_C];

    const int t = threadIdx.x;
    const long long e0 = (long long)blockIdx.x * ET;
    const long long e  = e0 + t;

    // weights / bins init
    for (int i = t; i < D_EDGE * HID; i += ET) sW[i] = g_WeT[i];
    if (t < HID) { sB[t] = g_bf[t]; sW2[t] = g_w2[t]; }
    if (t < N_GRAPHS_C) bins[t] = 0.0f;

    // issue gather loads early
    int src = 0, dst = 0;
    if (e < n_edges) {
        src = __ldg(ei + e);
        dst = __ldg(ei + n_edges + e);
    }
    int g = (e < n_edges) ? __ldg(batch + dst) : 0;
    float4 p0, p1, p2, p3;
    {
        const float4* pp = (const float4*)(g_p + (size_t)src * HID);
        p0 = __ldg(pp + 0); p1 = __ldg(pp + 1); p2 = __ldg(pp + 2); p3 = __ldg(pp + 3);
    }

    // stage edge_attr transposed into shared (coalesced gmem, conflict-free sts)
    const float4* ga = (const float4*)edge_attr + e0 * (D_EDGE / 4);
    const long long totalF4 = (long long)n_edges * (D_EDGE / 4);
#pragma unroll
    for (int r = 0; r < (ET * D_EDGE / 4) / ET; r++) {
        int idx = r * ET + t;                       // 0..2047
        float4 v = make_float4(0.f, 0.f, 0.f, 0.f);
        if (e0 * (D_EDGE / 4) + idx < totalF4) v = __ldg(ga + idx);
        int el = idx >> 3;                          // edge within tile
        int j4 = (idx & 7) * 4;
        sAttrT[(j4 + 0) * ST + el] = v.x;
        sAttrT[(j4 + 1) * ST + el] = v.y;
        sAttrT[(j4 + 2) * ST + el] = v.z;
        sAttrT[(j4 + 3) * ST + el] = v.w;
    }
    __syncthreads();

    float acc[HID];
    acc[0]  = p0.x + sB[0];  acc[1]  = p0.y + sB[1];  acc[2]  = p0.z + sB[2];  acc[3]  = p0.w + sB[3];
    acc[4]  = p1.x + sB[4];  acc[5]  = p1.y + sB[5];  acc[6]  = p1.z + sB[6];  acc[7]  = p1.w + sB[7];
    acc[8]  = p2.x + sB[8];  acc[9]  = p2.y + sB[9];  acc[10] = p2.z + sB[10]; acc[11] = p2.w + sB[11];
    acc[12] = p3.x + sB[12]; acc[13] = p3.y + sB[13]; acc[14] = p3.z + sB[14]; acc[15] = p3.w + sB[15];

#pragma unroll
    for (int j = 0; j < D_EDGE; j++) {
        float a = sAttrT[j * ST + t];
        const float4 w0 = *(const float4*)(sW + j * HID + 0);
        const float4 w1 = *(const float4*)(sW + j * HID + 4);
        const float4 w2 = *(const float4*)(sW + j * HID + 8);
        const float4 w3 = *(const float4*)(sW + j * HID + 12);
        acc[0]  += w0.x * a; acc[1]  += w0.y * a; acc[2]  += w0.z * a; acc[3]  += w0.w * a;
        acc[4]  += w1.x * a; acc[5]  += w1.y * a; acc[6]  += w1.z * a; acc[7]  += w1.w * a;
        acc[8]  += w2.x * a; acc[9]  += w2.y * a; acc[10] += w2.z * a; acc[11] += w2.w * a;
        acc[12] += w3.x * a; acc[13] += w3.y * a; acc[14] += w3.z * a; acc[15] += w3.w * a;
    }

    if (e < n_edges) {
        float msg = g_b2;
#pragma unroll
        for (int k = 0; k < HID; k++) msg += sW2[k] * fmaxf(acc[k], 0.0f);
        atomicAdd(&bins[g], msg);
    }
    __syncthreads();
    if (t < N_GRAPHS_C) {
        atomicAdd(&out[t], bins[t]);
    }
}

extern "C" void kernel_launch(void* const* d_in, const int* in_sizes, int n_in,
                              void* d_out, int out_size) {
    const float* x         = (const float*)d_in[0];
    const float* edge_attr = (const float*)d_in[1];
    const int*   ei        = (const int*)d_in[2];
    const int*   batch     = (const int*)d_in[3];
    const float* W1        = (const float*)d_in[4];
    const float* b1        = (const float*)d_in[5];
    const float* gamma     = (const float*)d_in[6];
    const float* beta      = (const float*)d_in[7];
    const float* rm        = (const float*)d_in[8];
    const float* rv        = (const float*)d_in[9];
    const float* W2        = (const float*)d_in[10];
    const float* b2        = (const float*)d_in[11];
    float* out = (float*)d_out;

    const int n_nodes = in_sizes[0] / D_NODE;
    const int n_edges = in_sizes[1] / D_EDGE;

    prep_kernel<<<1, 512>>>(W1, b1, gamma, beta, rm, rv, W2, b2);
    zero_kernel<<<1, 128>>>(out, out_size);
    node_kernel<<<(n_nodes + NT - 1) / NT, NT>>>(x, n_nodes);
    edge_kernel<<<(n_edges + ET - 1) / ET, ET>>>(edge_attr, ei, batch, out, n_edges);
}